// round 1
// baseline (speedup 1.0000x reference)
#include <cuda_runtime.h>
#include <math.h>

// Problem constants (fixed by reference setup_inputs)
#define B_ 2
#define E_ 32768
#define D_ 512
#define G_ 2048

// ---------------- scratch (static device allocations are the sanctioned path) ----
__device__ float    g_L[(size_t)B_ * E_ * D_];        // logits (B*E, D)  128MB
__device__ float    g_V[(size_t)B_ * E_ * D_];        // vals   (B*E, D)  128MB
__device__ unsigned g_menc[(size_t)G_ * B_ * D_];     // seg-max, sortable-uint encoded
__device__ float    g_denom[(size_t)G_ * B_ * D_];    // seg-sum of exp
__device__ float    g_ynum[(size_t)G_ * B_ * D_];     // seg-sum of exp*val
__device__ float    g_y[(size_t)B_ * G_ * D_];        // normalized (B,G,D)
__device__ float    g_of[(size_t)B_ * G_ * D_];       // h(y) (B,G,D)

// ---------------- float <-> order-preserving uint ---------------------------------
__device__ __forceinline__ unsigned f_enc(float f) {
    unsigned u = __float_as_uint(f);
    return (u & 0x80000000u) ? ~u : (u | 0x80000000u);
}
__device__ __forceinline__ float f_dec(unsigned u) {
    return __uint_as_float((u & 0x80000000u) ? (u ^ 0x80000000u) : ~u);
}

// ---------------- zero the reduction buffers --------------------------------------
__global__ void zero_k() {
    size_t n = (size_t)G_ * B_ * D_;
    size_t i = (size_t)blockIdx.x * blockDim.x + threadIdx.x;
    if (i < n) {
        g_menc[i]  = 0u;    // encodes -inf
        g_denom[i] = 0.0f;
        g_ynum[i]  = 0.0f;
    }
}

// ---------------- SGEMM: C[m][n] = sum_k A[m][k] * W[n][k] + bias[n] --------------
// A: (M,K) row-major, W: (N,K) row-major. M%128==0, N%128==0, K%16==0.
#define BM 128
#define BN 128
#define BKg 16
__global__ __launch_bounds__(256, 2)
void sgemm_nt(const float* __restrict__ A, const float* __restrict__ W,
              const float* __restrict__ bias, float* __restrict__ C,
              int M, int N, int K) {
    __shared__ float As[BKg][BM];
    __shared__ float Ws[BKg][BN];

    const int tid = threadIdx.x;          // 0..255
    const int tx  = tid & 15;             // n-direction
    const int ty  = tid >> 4;             // m-direction
    const int m0  = blockIdx.y * BM;
    const int n0  = blockIdx.x * BN;

    float acc[8][8];
#pragma unroll
    for (int i = 0; i < 8; i++)
#pragma unroll
        for (int j = 0; j < 8; j++) acc[i][j] = 0.0f;

    for (int k0 = 0; k0 < K; k0 += BKg) {
        // load A tile (BM x BKg) transposed into As[k][m]; 512 float4, 2 per thread
#pragma unroll
        for (int it = 0; it < 2; it++) {
            int i  = tid + it * 256;
            int r  = i >> 2;              // row within tile (0..127)
            int c4 = i & 3;               // float4 within the 16-wide k slab
            float4 v = *(const float4*)(A + (size_t)(m0 + r) * K + k0 + c4 * 4);
            As[c4 * 4 + 0][r] = v.x;
            As[c4 * 4 + 1][r] = v.y;
            As[c4 * 4 + 2][r] = v.z;
            As[c4 * 4 + 3][r] = v.w;
        }
        // load W tile (BN x BKg) transposed into Ws[k][n]
#pragma unroll
        for (int it = 0; it < 2; it++) {
            int i  = tid + it * 256;
            int r  = i >> 2;
            int c4 = i & 3;
            float4 v = *(const float4*)(W + (size_t)(n0 + r) * K + k0 + c4 * 4);
            Ws[c4 * 4 + 0][r] = v.x;
            Ws[c4 * 4 + 1][r] = v.y;
            Ws[c4 * 4 + 2][r] = v.z;
            Ws[c4 * 4 + 3][r] = v.w;
        }
        __syncthreads();

#pragma unroll
        for (int k = 0; k < BKg; k++) {
            float am[8], wn[8];
#pragma unroll
            for (int i = 0; i < 8; i++) am[i] = As[k][ty * 8 + i];
#pragma unroll
            for (int j = 0; j < 8; j++) wn[j] = Ws[k][tx * 8 + j];
#pragma unroll
            for (int i = 0; i < 8; i++)
#pragma unroll
                for (int j = 0; j < 8; j++) acc[i][j] += am[i] * wn[j];
        }
        __syncthreads();
    }

    float bs[8];
#pragma unroll
    for (int j = 0; j < 8; j++) bs[j] = bias[n0 + tx * 8 + j];

#pragma unroll
    for (int i = 0; i < 8; i++) {
        size_t row = (size_t)(m0 + ty * 8 + i);
        float4* cp = (float4*)(C + row * N + n0 + tx * 8);
        float4 v0, v1;
        v0.x = acc[i][0] + bs[0]; v0.y = acc[i][1] + bs[1];
        v0.z = acc[i][2] + bs[2]; v0.w = acc[i][3] + bs[3];
        v1.x = acc[i][4] + bs[4]; v1.y = acc[i][5] + bs[5];
        v1.z = acc[i][6] + bs[6]; v1.w = acc[i][7] + bs[7];
        cp[0] = v0;
        cp[1] = v1;
    }
}

// ---------------- segment max (atomicMax on sortable uints) -----------------------
__global__ void segmax_k(const int* __restrict__ ix) {
    size_t i = (size_t)blockIdx.x * blockDim.x + threadIdx.x;  // over (b,e,d)
    if (i >= (size_t)B_ * E_ * D_) return;
    int    d  = (int)(i % D_);
    size_t be = i / D_;
    int    e  = (int)(be % E_);
    int    b  = (int)(be / E_);
    int    g  = ix[e];
    atomicMax(&g_menc[((size_t)g * B_ + b) * D_ + d], f_enc(g_L[i]));
}

// ---------------- exp + fused denom / numerator accumulation ----------------------
__global__ void segexp_k(const int* __restrict__ ix) {
    size_t i = (size_t)blockIdx.x * blockDim.x + threadIdx.x;  // over (b,e,d)
    if (i >= (size_t)B_ * E_ * D_) return;
    int    d  = (int)(i % D_);
    size_t be = i / D_;
    int    e  = (int)(be % E_);
    int    b  = (int)(be / E_);
    int    g  = ix[e];
    size_t t  = ((size_t)g * B_ + b) * D_ + d;
    float  m  = f_dec(g_menc[t]);
    float  ev = expf(g_L[i] - m);
    atomicAdd(&g_denom[t], ev);
    atomicAdd(&g_ynum[t], ev * g_V[i]);
}

// ---------------- normalize into (B,G,D) layout -----------------------------------
__global__ void norm_k() {
    size_t i = (size_t)blockIdx.x * blockDim.x + threadIdx.x;  // over (b,g,d)
    if (i >= (size_t)B_ * G_ * D_) return;
    int    d  = (int)(i % D_);
    size_t bg = i / D_;
    int    g  = (int)(bg % G_);
    int    b  = (int)(bg / G_);
    size_t t  = ((size_t)g * B_ + b) * D_ + d;
    float  den = g_denom[t];
    g_y[i] = (den > 0.0f) ? (g_ynum[t] / den) : 0.0f;
}

// ---------------- gather out[b,e,:] = of[b, ix[e], :] -----------------------------
__global__ void gather_k(const int* __restrict__ ix, float4* __restrict__ out) {
    size_t i = (size_t)blockIdx.x * blockDim.x + threadIdx.x;  // over (b,e,d/4)
    const size_t n4 = (size_t)B_ * E_ * (D_ / 4);
    if (i >= n4) return;
    int    d4 = (int)(i % (D_ / 4));
    size_t be = i / (D_ / 4);
    int    e  = (int)(be % E_);
    int    b  = (int)(be / E_);
    const float4* of4 = (const float4*)g_of;
    out[i] = of4[((size_t)b * G_ + ix[e]) * (D_ / 4) + d4];
}

// ---------------- launcher ---------------------------------------------------------
extern "C" void kernel_launch(void* const* d_in, const int* in_sizes, int n_in,
                              void* d_out, int out_size) {
    const float* x  = (const float*)d_in[0];
    const int*   ix = (const int*)d_in[1];
    const float* Wf = (const float*)d_in[2];
    const float* bf = (const float*)d_in[3];
    const float* Wg = (const float*)d_in[4];
    const float* bg = (const float*)d_in[5];
    const float* Wh = (const float*)d_in[6];
    const float* bh = (const float*)d_in[7];
    float* out = (float*)d_out;

    float* pL;  cudaGetSymbolAddress((void**)&pL, g_L);
    float* pV;  cudaGetSymbolAddress((void**)&pV, g_V);
    float* pY;  cudaGetSymbolAddress((void**)&pY, g_y);
    float* pOF; cudaGetSymbolAddress((void**)&pOF, g_of);

    const int T = 256;

    // 1) reset reduction buffers
    {
        size_t n = (size_t)G_ * B_ * D_;
        zero_k<<<(unsigned)((n + T - 1) / T), T>>>();
    }

    // 2) projections: L = X@Wg^T + bg ; V = X@Wf^T + bf   (M = B*E)
    {
        dim3 grid(D_ / BN, (B_ * E_) / BM);
        sgemm_nt<<<grid, T>>>(x, Wg, bg, pL, B_ * E_, D_, D_);
        sgemm_nt<<<grid, T>>>(x, Wf, bf, pV, B_ * E_, D_, D_);
    }

    // 3) segment max
    {
        size_t n = (size_t)B_ * E_ * D_;
        segmax_k<<<(unsigned)((n + T - 1) / T), T>>>(ix);
    }

    // 4) exp + fused denominator / numerator scatter-sums
    {
        size_t n = (size_t)B_ * E_ * D_;
        segexp_k<<<(unsigned)((n + T - 1) / T), T>>>(ix);
    }

    // 5) normalize y = ynum / denom into (B,G,D)
    {
        size_t n = (size_t)B_ * G_ * D_;
        norm_k<<<(unsigned)((n + T - 1) / T), T>>>();
    }

    // 6) out_full = y @ Wh^T + bh   (M = B*G = 4096)
    {
        dim3 grid(D_ / BN, (B_ * G_) / BM);
        sgemm_nt<<<grid, T>>>(pY, Wh, bh, pOF, B_ * G_, D_, D_);
    }

    // 7) gather to edges
    {
        size_t n4 = (size_t)B_ * E_ * (D_ / 4);
        gather_k<<<(unsigned)((n4 + T - 1) / T), T>>>(ix, (float4*)out);
    }
}

// round 3
// speedup vs baseline: 2.4727x; 2.4727x over previous
#include <cuda_runtime.h>
#include <cuda_bf16.h>
#include <cstdint>
#include <math.h>

#define B_ 2
#define E_ 32768
#define D_ 512
#define G_ 2048

// ---------------- scratch ------------------------------------------------------------
__device__ float         g_LV[(size_t)B_ * E_ * 1024];     // [m, 0:512]=logits, [m,512:1024]=vals
__device__ __nv_bfloat16 g_xhi[(size_t)B_ * E_ * D_];
__device__ __nv_bfloat16 g_xlo[(size_t)B_ * E_ * D_];
__device__ __nv_bfloat16 g_wstkhi[1024 * 512], g_wstklo[1024 * 512];  // [Wg; Wf]
__device__ float         g_bstk[1024];
__device__ __nv_bfloat16 g_whhi[D_ * D_], g_whlo[D_ * D_];
__device__ __nv_bfloat16 g_yhi[(size_t)B_ * G_ * D_], g_ylo[(size_t)B_ * G_ * D_];
__device__ float         g_of[(size_t)B_ * G_ * D_];
__device__ int           g_cnt[G_], g_start[G_ + 1], g_cursor[G_], g_order[E_];

// ---------------- PTX helpers ---------------------------------------------------------
__device__ __forceinline__ uint32_t smem_u32(const void* p) {
    uint32_t a;
    asm("{ .reg .u64 t; cvta.to.shared.u64 t, %1; cvt.u32.u64 %0, t; }" : "=r"(a) : "l"(p));
    return a;
}
__device__ __forceinline__ void cp16(uint32_t s, const void* g) {
    asm volatile("cp.async.cg.shared.global [%0], [%1], 16;" :: "r"(s), "l"(g));
}
#define CP_COMMIT() asm volatile("cp.async.commit_group;" ::: "memory")
#define CP_WAIT(n)  asm volatile("cp.async.wait_group %0;" :: "n"(n) : "memory")

__device__ __forceinline__ void ldsm4(uint32_t* r, uint32_t addr) {
    asm volatile("ldmatrix.sync.aligned.m8n8.x4.shared.b16 {%0,%1,%2,%3}, [%4];"
                 : "=r"(r[0]), "=r"(r[1]), "=r"(r[2]), "=r"(r[3]) : "r"(addr));
}
__device__ __forceinline__ void ldsm2(uint32_t* r, uint32_t addr) {
    asm volatile("ldmatrix.sync.aligned.m8n8.x2.shared.b16 {%0,%1}, [%2];"
                 : "=r"(r[0]), "=r"(r[1]) : "r"(addr));
}
__device__ __forceinline__ void mma_bf16(float* c, const uint32_t* a, const uint32_t* b) {
    asm volatile(
        "mma.sync.aligned.m16n8k16.row.col.f32.bf16.bf16.f32 "
        "{%0,%1,%2,%3}, {%4,%5,%6,%7}, {%8,%9}, {%0,%1,%2,%3};"
        : "+f"(c[0]), "+f"(c[1]), "+f"(c[2]), "+f"(c[3])
        : "r"(a[0]), "r"(a[1]), "r"(a[2]), "r"(a[3]), "r"(b[0]), "r"(b[1]));
}

// ---------------- hi/lo split conversion (float4 vectorized) ---------------------------
__global__ void cvt_hilo4(const float* __restrict__ s, __nv_bfloat16* __restrict__ hi,
                          __nv_bfloat16* __restrict__ lo, size_t n4) {
    size_t i = (size_t)blockIdx.x * blockDim.x + threadIdx.x;
    if (i >= n4) return;
    float4 f = ((const float4*)s)[i];
    __nv_bfloat16 h0 = __float2bfloat16(f.x), h1 = __float2bfloat16(f.y);
    __nv_bfloat16 h2 = __float2bfloat16(f.z), h3 = __float2bfloat16(f.w);
    __nv_bfloat16 l0 = __float2bfloat16(f.x - __bfloat162float(h0));
    __nv_bfloat16 l1 = __float2bfloat16(f.y - __bfloat162float(h1));
    __nv_bfloat16 l2 = __float2bfloat16(f.z - __bfloat162float(h2));
    __nv_bfloat16 l3 = __float2bfloat16(f.w - __bfloat162float(h3));
    ((__nv_bfloat162*)hi)[2 * i]     = __halves2bfloat162(h0, h1);
    ((__nv_bfloat162*)hi)[2 * i + 1] = __halves2bfloat162(h2, h3);
    ((__nv_bfloat162*)lo)[2 * i]     = __halves2bfloat162(l0, l1);
    ((__nv_bfloat162*)lo)[2 * i + 1] = __halves2bfloat162(l2, l3);
}

__global__ void stack_bias(const float* __restrict__ bg, const float* __restrict__ bf) {
    int t = threadIdx.x + blockIdx.x * blockDim.x;
    if (t < 512) { g_bstk[t] = bg[t]; g_bstk[512 + t] = bf[t]; }
}

// ---------------- CSR build -------------------------------------------------------------
__global__ void zero_cnt() {
    int t = threadIdx.x + blockIdx.x * blockDim.x;
    if (t < G_) g_cnt[t] = 0;
}
__global__ void hist_k(const int* __restrict__ ix) {
    int e = threadIdx.x + blockIdx.x * blockDim.x;
    if (e < E_) atomicAdd(&g_cnt[ix[e]], 1);
}
__global__ void scan_k() {   // 1 block, 1024 threads, 2 elems each
    __shared__ int ps[1024];
    int t = threadIdx.x;
    int c0 = g_cnt[2 * t], c1 = g_cnt[2 * t + 1];
    ps[t] = c0 + c1;
    __syncthreads();
#pragma unroll
    for (int off = 1; off < 1024; off <<= 1) {
        int v = (t >= off) ? ps[t - off] : 0;
        __syncthreads();
        ps[t] += v;
        __syncthreads();
    }
    int excl = (t > 0) ? ps[t - 1] : 0;
    g_start[2 * t] = excl;          g_cursor[2 * t] = excl;
    g_start[2 * t + 1] = excl + c0; g_cursor[2 * t + 1] = excl + c0;
    if (t == 1023) g_start[2048] = ps[1023];
}
__global__ void scatter_k(const int* __restrict__ ix) {
    int e = threadIdx.x + blockIdx.x * blockDim.x;
    if (e >= E_) return;
    int idx = atomicAdd(&g_cursor[ix[e]], 1);
    g_order[idx] = e;
}

// ---------------- bf16x3 GEMM on mma.sync ------------------------------------------------
// C[m][n] = sum_k A[m][k]*W[n][k] + bias[n]. K=512. CTA tile 128x256, BK=32, 512 thr.
// SMEM: 80B row pitch (conflict-free ldmatrix). Double-buffered cp.async.
#define PITCH 80
#define ABUF  10240            // 128 rows * 80
#define BBUF  20480            // 256 rows * 80
#define BUFSZ 61440            // Ah + Al + Bh + Bl
#define SMEM_GEMM (2 * BUFSZ)  // 122880

__global__ __launch_bounds__(512, 1)
void gemm3(const __nv_bfloat16* __restrict__ Ahi, const __nv_bfloat16* __restrict__ Alo,
           const __nv_bfloat16* __restrict__ Bhi, const __nv_bfloat16* __restrict__ Blo,
           const float* __restrict__ bias, float* __restrict__ C, int ldc) {
    extern __shared__ char smem[];
    const uint32_t sb = smem_u32(smem);
    const int tid = threadIdx.x, lane = tid & 31, wid = tid >> 5;
    const int wm = wid >> 2, wn = wid & 3;            // 4x4 warps, warp tile 32x64
    const int m0 = blockIdx.y * 128, n0 = blockIdx.x * 256;

    float acc[2][8][4];
#pragma unroll
    for (int mt = 0; mt < 2; mt++)
#pragma unroll
        for (int nt = 0; nt < 8; nt++)
#pragma unroll
            for (int q = 0; q < 4; q++) acc[mt][nt][q] = 0.0f;

    // cp.async loader: 3072 16B chunks per buffer, 6 per thread
    auto load_buf = [&](int kc, int buf) {
        const int k0 = kc * 32;
        const uint32_t bb = sb + buf * BUFSZ;
#pragma unroll
        for (int t = 0; t < 6; t++) {
            int q = tid + t * 512;
            int region = q >> 10;                  // 0:Ah 1:Al 2:Bh(+/2048 Bl)
            const __nv_bfloat16* src;
            uint32_t base;
            int qq;
            if (q < 512)        { src = Ahi; base = 0;           qq = q; }
            else if (q < 1024)  { src = Alo; base = ABUF;        qq = q - 512; }
            else if (q < 2048)  { src = Bhi; base = 2 * ABUF;    qq = q - 1024; }
            else                { src = Blo; base = 2*ABUF+BBUF; qq = q - 2048; }
            (void)region;
            int row = qq >> 2, c = qq & 3;
            int grow = (q < 1024) ? (m0 + row) : (n0 + row);
            cp16(bb + base + (uint32_t)(row * PITCH + c * 16),
                 src + (size_t)grow * 512 + k0 + c * 8);
        }
    };

    load_buf(0, 0);
    CP_COMMIT();

    for (int kc = 0; kc < 16; kc++) {
        if (kc < 15) { load_buf(kc + 1, (kc + 1) & 1); CP_COMMIT(); CP_WAIT(1); }
        else         { CP_WAIT(0); }
        __syncthreads();

        const uint32_t bb = sb + (kc & 1) * BUFSZ;
#pragma unroll
        for (int ks = 0; ks < 2; ks++) {
            uint32_t ah[2][4], al[2][4];
            uint32_t aoff = (uint32_t)((wm * 32 + (lane & 15)) * PITCH +
                                       ((lane >> 4) * 16) + ks * 32);
#pragma unroll
            for (int mt = 0; mt < 2; mt++) {
                ldsm4(ah[mt], bb + aoff + (uint32_t)(mt * 16 * PITCH));
                ldsm4(al[mt], bb + ABUF + aoff + (uint32_t)(mt * 16 * PITCH));
            }
            uint32_t boff = (uint32_t)((wn * 64 + (lane & 7)) * PITCH +
                                       (((lane >> 3) & 1) * 16) + ks * 32);
#pragma unroll
            for (int nt = 0; nt < 8; nt++) {
                uint32_t bh[2], bl[2];
                ldsm2(bh, bb + 2 * ABUF + boff + (uint32_t)(nt * 8 * PITCH));
                ldsm2(bl, bb + 2 * ABUF + BBUF + boff + (uint32_t)(nt * 8 * PITCH));
#pragma unroll
                for (int mt = 0; mt < 2; mt++) {
                    mma_bf16(acc[mt][nt], ah[mt], bh);
                    mma_bf16(acc[mt][nt], ah[mt], bl);
                    mma_bf16(acc[mt][nt], al[mt], bh);
                }
            }
        }
        __syncthreads();
    }

    // epilogue: bias + direct stores
#pragma unroll
    for (int mt = 0; mt < 2; mt++) {
        int r0 = m0 + wm * 32 + mt * 16 + (lane >> 2);
#pragma unroll
        for (int nt = 0; nt < 8; nt++) {
            int col = n0 + wn * 64 + nt * 8 + (lane & 3) * 2;
            float b0 = bias[col], b1 = bias[col + 1];
            float2 v0 = make_float2(acc[mt][nt][0] + b0, acc[mt][nt][1] + b1);
            float2 v1 = make_float2(acc[mt][nt][2] + b0, acc[mt][nt][3] + b1);
            *(float2*)&C[(size_t)r0 * ldc + col]       = v0;
            *(float2*)&C[(size_t)(r0 + 8) * ldc + col] = v1;
        }
    }
}

// ---------------- per-group softmax-weighted reduction -----------------------------------
// One block per (g, b). Reads CSR edges, computes denom & weighted sum over edges,
// writes y = num/denom directly as hi/lo bf16 (fused normalize + convert).
__global__ __launch_bounds__(128)
void segreduce_k() {
    int g = blockIdx.x, b = blockIdx.y;
    int t = threadIdx.x;                 // t covers d = 4t..4t+3
    int s = g_start[g], e_end = g_start[g + 1];

    float4 den = make_float4(0.f, 0.f, 0.f, 0.f);
    float4 num = make_float4(0.f, 0.f, 0.f, 0.f);
    const float4* LV4 = (const float4*)g_LV;

    for (int j = s; j < e_end; j++) {
        int e = g_order[j];
        size_t row = (size_t)b * E_ + e;
        float4 L = LV4[row * 256 + t];
        float4 V = LV4[row * 256 + 128 + t];
        float e0 = __expf(L.x), e1 = __expf(L.y), e2 = __expf(L.z), e3 = __expf(L.w);
        den.x += e0; den.y += e1; den.z += e2; den.w += e3;
        num.x += e0 * V.x; num.y += e1 * V.y; num.z += e2 * V.z; num.w += e3 * V.w;
    }
    float y0 = (den.x > 0.f) ? num.x / den.x : 0.f;
    float y1 = (den.y > 0.f) ? num.y / den.y : 0.f;
    float y2 = (den.z > 0.f) ? num.z / den.z : 0.f;
    float y3 = (den.w > 0.f) ? num.w / den.w : 0.f;

    __nv_bfloat16 h0 = __float2bfloat16(y0), h1 = __float2bfloat16(y1);
    __nv_bfloat16 h2 = __float2bfloat16(y2), h3 = __float2bfloat16(y3);
    __nv_bfloat16 l0 = __float2bfloat16(y0 - __bfloat162float(h0));
    __nv_bfloat16 l1 = __float2bfloat16(y1 - __bfloat162float(h1));
    __nv_bfloat16 l2 = __float2bfloat16(y2 - __bfloat162float(h2));
    __nv_bfloat16 l3 = __float2bfloat16(y3 - __bfloat162float(h3));

    size_t o2 = ((size_t)b * G_ + g) * 256 + (size_t)t * 2;   // bf16x2 index
    ((__nv_bfloat162*)g_yhi)[o2]     = __halves2bfloat162(h0, h1);
    ((__nv_bfloat162*)g_yhi)[o2 + 1] = __halves2bfloat162(h2, h3);
    ((__nv_bfloat162*)g_ylo)[o2]     = __halves2bfloat162(l0, l1);
    ((__nv_bfloat162*)g_ylo)[o2 + 1] = __halves2bfloat162(l2, l3);
}

// ---------------- gather out[b,e,:] = of[b, ix[e], :] -------------------------------------
__global__ void gather_k(const int* __restrict__ ix, float4* __restrict__ out) {
    size_t i = (size_t)blockIdx.x * blockDim.x + threadIdx.x;
    const size_t n4 = (size_t)B_ * E_ * (D_ / 4);
    if (i >= n4) return;
    int    d4 = (int)(i & 127);
    size_t be = i >> 7;
    int    e  = (int)(be & (E_ - 1));
    int    b  = (int)(be >> 15);
    const float4* of4 = (const float4*)g_of;
    out[i] = of4[((size_t)b * G_ + ix[e]) * 128 + d4];
}

// ---------------- launcher -----------------------------------------------------------------
extern "C" void kernel_launch(void* const* d_in, const int* in_sizes, int n_in,
                              void* d_out, int out_size) {
    const float* x  = (const float*)d_in[0];
    const int*   ix = (const int*)d_in[1];
    const float* Wf = (const float*)d_in[2];
    const float* bf = (const float*)d_in[3];
    const float* Wg = (const float*)d_in[4];
    const float* bg = (const float*)d_in[5];
    const float* Wh = (const float*)d_in[6];
    const float* bh = (const float*)d_in[7];
    float* out = (float*)d_out;

    float* pLV;  cudaGetSymbolAddress((void**)&pLV, g_LV);
    float* pOF;  cudaGetSymbolAddress((void**)&pOF, g_of);
    __nv_bfloat16 *xhi, *xlo, *wshi, *wslo, *whhi, *whlo, *yhi, *ylo;
    cudaGetSymbolAddress((void**)&xhi, g_xhi);
    cudaGetSymbolAddress((void**)&xlo, g_xlo);
    cudaGetSymbolAddress((void**)&wshi, g_wstkhi);
    cudaGetSymbolAddress((void**)&wslo, g_wstklo);
    cudaGetSymbolAddress((void**)&whhi, g_whhi);
    cudaGetSymbolAddress((void**)&whlo, g_whlo);
    cudaGetSymbolAddress((void**)&yhi, g_yhi);
    cudaGetSymbolAddress((void**)&ylo, g_ylo);
    float* pbstk; cudaGetSymbolAddress((void**)&pbstk, g_bstk);

    cudaFuncSetAttribute(gemm3, cudaFuncAttributeMaxDynamicSharedMemorySize, SMEM_GEMM);

    const int T = 256;

    // 0) conversions: x -> hi/lo; Wg/Wf stacked; Wh; bias stack
    {
        size_t n4 = (size_t)B_ * E_ * D_ / 4;
        cvt_hilo4<<<(unsigned)((n4 + T - 1) / T), T>>>(x, xhi, xlo, n4);
        size_t w4 = (size_t)D_ * D_ / 4;
        cvt_hilo4<<<(unsigned)((w4 + T - 1) / T), T>>>(Wg, wshi, wslo, w4);
        cvt_hilo4<<<(unsigned)((w4 + T - 1) / T), T>>>(Wf, wshi + 512 * 512, wslo + 512 * 512, w4);
        cvt_hilo4<<<(unsigned)((w4 + T - 1) / T), T>>>(Wh, whhi, whlo, w4);
        stack_bias<<<2, 256>>>(bg, bf);
    }

    // 1) CSR build from ix
    zero_cnt<<<G_ / T, T>>>();
    hist_k<<<E_ / T, T>>>(ix);
    scan_k<<<1, 1024>>>();
    scatter_k<<<E_ / T, T>>>(ix);

    // 2) projections (stacked): LV = X @ [Wg;Wf]^T + [bg;bf]
    {
        dim3 grid(4, (B_ * E_) / 128);
        gemm3<<<grid, 512, SMEM_GEMM>>>(xhi, xlo, wshi, wslo, pbstk, pLV, 1024);
    }

    // 3) per-group softmax-weighted reduce -> y (hi/lo bf16, fused)
    {
        dim3 grid(G_, B_);
        segreduce_k<<<grid, 128>>>();
    }

    // 4) of = y @ Wh^T + bh
    {
        dim3 grid(2, (B_ * G_) / 128);
        gemm3<<<grid, 512, SMEM_GEMM>>>(yhi, ylo, whhi, whlo, bh, pOF, 512);
    }

    // 5) gather to edges
    {
        size_t n4 = (size_t)B_ * E_ * (D_ / 4);
        gather_k<<<(unsigned)((n4 + T - 1) / T), T>>>(ix, (float4*)out);
    }
}

// round 4
// speedup vs baseline: 2.7118x; 1.0967x over previous
#include <cuda_runtime.h>
#include <cuda_bf16.h>
#include <cstdint>
#include <math.h>

#define B_ 2
#define E_ 32768
#define D_ 512
#define G_ 2048

// ---------------- scratch ------------------------------------------------------------
__device__ float         g_LV[(size_t)B_ * E_ * 1024];     // [m, 0:512]=logits, [m,512:1024]=vals
__device__ __nv_bfloat16 g_xhi[(size_t)B_ * E_ * D_];
__device__ __nv_bfloat16 g_xlo[(size_t)B_ * E_ * D_];
__device__ __nv_bfloat16 g_wstkhi[1024 * 512], g_wstklo[1024 * 512];  // [Wg; Wf]
__device__ float         g_bstk[1024];
__device__ __nv_bfloat16 g_whhi[D_ * D_], g_whlo[D_ * D_];
__device__ __nv_bfloat16 g_yhi[(size_t)B_ * G_ * D_], g_ylo[(size_t)B_ * G_ * D_];
__device__ float         g_of[(size_t)B_ * G_ * D_];
__device__ int           g_cnt[G_], g_start[G_ + 1], g_cursor[G_], g_order[E_];

// ---------------- PTX helpers ---------------------------------------------------------
__device__ __forceinline__ uint32_t smem_u32(const void* p) {
    uint32_t a;
    asm("{ .reg .u64 t; cvta.to.shared.u64 t, %1; cvt.u32.u64 %0, t; }" : "=r"(a) : "l"(p));
    return a;
}
__device__ __forceinline__ void cp16(uint32_t s, const void* g) {
    asm volatile("cp.async.cg.shared.global [%0], [%1], 16;" :: "r"(s), "l"(g));
}
#define CP_COMMIT() asm volatile("cp.async.commit_group;" ::: "memory")
#define CP_WAIT(n)  asm volatile("cp.async.wait_group %0;" :: "n"(n) : "memory")

__device__ __forceinline__ void ldsm4(uint32_t* r, uint32_t addr) {
    asm volatile("ldmatrix.sync.aligned.m8n8.x4.shared.b16 {%0,%1,%2,%3}, [%4];"
                 : "=r"(r[0]), "=r"(r[1]), "=r"(r[2]), "=r"(r[3]) : "r"(addr));
}
__device__ __forceinline__ void mma_bf16(float* c, const uint32_t* a, const uint32_t* b) {
    asm volatile(
        "mma.sync.aligned.m16n8k16.row.col.f32.bf16.bf16.f32 "
        "{%0,%1,%2,%3}, {%4,%5,%6,%7}, {%8,%9}, {%0,%1,%2,%3};"
        : "+f"(c[0]), "+f"(c[1]), "+f"(c[2]), "+f"(c[3])
        : "r"(a[0]), "r"(a[1]), "r"(a[2]), "r"(a[3]), "r"(b[0]), "r"(b[1]));
}

// ---------------- hi/lo split conversion (float4 vectorized) ---------------------------
__global__ void cvt_hilo4(const float* __restrict__ s, __nv_bfloat16* __restrict__ hi,
                          __nv_bfloat16* __restrict__ lo, size_t n4) {
    size_t i = (size_t)blockIdx.x * blockDim.x + threadIdx.x;
    if (i >= n4) return;
    float4 f = ((const float4*)s)[i];
    __nv_bfloat16 h0 = __float2bfloat16(f.x), h1 = __float2bfloat16(f.y);
    __nv_bfloat16 h2 = __float2bfloat16(f.z), h3 = __float2bfloat16(f.w);
    __nv_bfloat16 l0 = __float2bfloat16(f.x - __bfloat162float(h0));
    __nv_bfloat16 l1 = __float2bfloat16(f.y - __bfloat162float(h1));
    __nv_bfloat16 l2 = __float2bfloat16(f.z - __bfloat162float(h2));
    __nv_bfloat16 l3 = __float2bfloat16(f.w - __bfloat162float(h3));
    ((__nv_bfloat162*)hi)[2 * i]     = __halves2bfloat162(h0, h1);
    ((__nv_bfloat162*)hi)[2 * i + 1] = __halves2bfloat162(h2, h3);
    ((__nv_bfloat162*)lo)[2 * i]     = __halves2bfloat162(l0, l1);
    ((__nv_bfloat162*)lo)[2 * i + 1] = __halves2bfloat162(l2, l3);
}

__global__ void stack_bias(const float* __restrict__ bg, const float* __restrict__ bf) {
    int t = threadIdx.x + blockIdx.x * blockDim.x;
    if (t < 512) { g_bstk[t] = bg[t]; g_bstk[512 + t] = bf[t]; }
}

// ---------------- CSR build -------------------------------------------------------------
__global__ void zero_cnt() {
    int t = threadIdx.x + blockIdx.x * blockDim.x;
    if (t < G_) g_cnt[t] = 0;
}
__global__ void hist_k(const int* __restrict__ ix) {
    int e = threadIdx.x + blockIdx.x * blockDim.x;
    if (e < E_) atomicAdd(&g_cnt[ix[e]], 1);
}
__global__ void scan_k() {   // 1 block, 1024 threads, 2 elems each
    __shared__ int ps[1024];
    int t = threadIdx.x;
    int c0 = g_cnt[2 * t], c1 = g_cnt[2 * t + 1];
    ps[t] = c0 + c1;
    __syncthreads();
#pragma unroll
    for (int off = 1; off < 1024; off <<= 1) {
        int v = (t >= off) ? ps[t - off] : 0;
        __syncthreads();
        ps[t] += v;
        __syncthreads();
    }
    int excl = (t > 0) ? ps[t - 1] : 0;
    g_start[2 * t] = excl;          g_cursor[2 * t] = excl;
    g_start[2 * t + 1] = excl + c0; g_cursor[2 * t + 1] = excl + c0;
    if (t == 1023) g_start[2048] = ps[1023];
}
__global__ void scatter_k(const int* __restrict__ ix) {
    int e = threadIdx.x + blockIdx.x * blockDim.x;
    if (e >= E_) return;
    int idx = atomicAdd(&g_cursor[ix[e]], 1);
    g_order[idx] = e;
}

// ---------------- bf16x3 GEMM on mma.sync, 3-stage pipeline ------------------------------
// C[m][n] = sum_k A[m][k]*W[n][k] + bias[n]. K=512. CTA tile 128x256, BK=32, 512 thr.
// 80B smem row pitch (conflict-free ldmatrix), 3-stage cp.async, 1 sync per K-iter.
#define PITCH 80
#define ABUF  10240            // 128 rows * 80
#define BBUF  20480            // 256 rows * 80
#define BUFSZ 61440            // Ah + Al + Bh + Bl per stage
#define NSTAGE 3
#define SMEM_GEMM (NSTAGE * BUFSZ)  // 184320

__global__ __launch_bounds__(512, 1)
void gemm3(const __nv_bfloat16* __restrict__ Ahi, const __nv_bfloat16* __restrict__ Alo,
           const __nv_bfloat16* __restrict__ Bhi, const __nv_bfloat16* __restrict__ Blo,
           const float* __restrict__ bias, float* __restrict__ C, int ldc) {
    extern __shared__ char smem[];
    const uint32_t sb = smem_u32(smem);
    const int tid = threadIdx.x, lane = tid & 31, wid = tid >> 5;
    const int wm = wid >> 2, wn = wid & 3;            // 4x4 warps, warp tile 32x64
    const int m0 = blockIdx.y * 128, n0 = blockIdx.x * 256;

    float acc[2][8][4];
#pragma unroll
    for (int mt = 0; mt < 2; mt++)
#pragma unroll
        for (int nt = 0; nt < 8; nt++)
#pragma unroll
            for (int q = 0; q < 4; q++) acc[mt][nt][q] = 0.0f;

    // cp.async loader: 3072 16B chunks per stage, 6 per thread
    auto load_buf = [&](int kc, int buf) {
        const int k0 = kc * 32;
        const uint32_t bb = sb + buf * BUFSZ;
#pragma unroll
        for (int t = 0; t < 6; t++) {
            int q = tid + t * 512;
            const __nv_bfloat16* src;
            uint32_t base;
            int qq;
            if (q < 512)        { src = Ahi; base = 0;           qq = q; }
            else if (q < 1024)  { src = Alo; base = ABUF;        qq = q - 512; }
            else if (q < 2048)  { src = Bhi; base = 2 * ABUF;    qq = q - 1024; }
            else                { src = Blo; base = 2*ABUF+BBUF; qq = q - 2048; }
            int row = qq >> 2, c = qq & 3;
            int grow = (q < 1024) ? (m0 + row) : (n0 + row);
            cp16(bb + base + (uint32_t)(row * PITCH + c * 16),
                 src + (size_t)grow * 512 + k0 + c * 8);
        }
    };

    load_buf(0, 0); CP_COMMIT();
    load_buf(1, 1); CP_COMMIT();

    // A-fragment lane addressing (row-major A, m16k16 tiles)
    const uint32_t a_lane = (uint32_t)((wm * 32 + (lane & 15)) * PITCH + (lane >> 4) * 16);
    // B-fragment lane addressing for ldsm4 over an n16 x k16 block:
    //   m0: rows n0-7 @k0-7, m1: rows n0-7 @k8-15, m2: rows n8-15 @k0-7, m3: rows n8-15 @k8-15
    const uint32_t b_lane = (uint32_t)((wn * 64 + ((lane >> 4) & 1) * 8 + (lane & 7)) * PITCH +
                                       ((lane >> 3) & 1) * 16);

    for (int kc = 0; kc < 16; kc++) {
        CP_WAIT(1);
        __syncthreads();
        if (kc + 2 < 16) load_buf(kc + 2, (kc + 2) % NSTAGE);
        CP_COMMIT();

        const uint32_t bb = sb + (kc % NSTAGE) * BUFSZ;
#pragma unroll
        for (int ks = 0; ks < 2; ks++) {
            uint32_t ah[2][4], al[2][4];
            uint32_t aoff = a_lane + (uint32_t)(ks * 32);
            ldsm4(ah[0], bb + aoff);
            ldsm4(ah[1], bb + aoff + 16 * PITCH);
            ldsm4(al[0], bb + ABUF + aoff);
            ldsm4(al[1], bb + ABUF + aoff + 16 * PITCH);
#pragma unroll
            for (int np = 0; np < 4; np++) {
                uint32_t boff = b_lane + (uint32_t)(np * 16 * PITCH + ks * 32);
                uint32_t bh4[4], bl4[4];
                ldsm4(bh4, bb + 2 * ABUF + boff);
                ldsm4(bl4, bb + 2 * ABUF + BBUF + boff);
#pragma unroll
                for (int mt = 0; mt < 2; mt++) {
                    mma_bf16(acc[mt][2 * np],     ah[mt], bh4);
                    mma_bf16(acc[mt][2 * np + 1], ah[mt], bh4 + 2);
                    mma_bf16(acc[mt][2 * np],     ah[mt], bl4);
                    mma_bf16(acc[mt][2 * np + 1], ah[mt], bl4 + 2);
                    mma_bf16(acc[mt][2 * np],     al[mt], bh4);
                    mma_bf16(acc[mt][2 * np + 1], al[mt], bh4 + 2);
                }
            }
        }
    }

    // epilogue: bias + direct stores
#pragma unroll
    for (int mt = 0; mt < 2; mt++) {
        int r0 = m0 + wm * 32 + mt * 16 + (lane >> 2);
#pragma unroll
        for (int nt = 0; nt < 8; nt++) {
            int col = n0 + wn * 64 + nt * 8 + (lane & 3) * 2;
            float b0 = bias[col], b1 = bias[col + 1];
            float2 v0 = make_float2(acc[mt][nt][0] + b0, acc[mt][nt][1] + b1);
            float2 v1 = make_float2(acc[mt][nt][2] + b0, acc[mt][nt][3] + b1);
            *(float2*)&C[(size_t)r0 * ldc + col]       = v0;
            *(float2*)&C[(size_t)(r0 + 8) * ldc + col] = v1;
        }
    }
}

// ---------------- per-group softmax-weighted reduction -----------------------------------
__global__ __launch_bounds__(128)
void segreduce_k() {
    int g = blockIdx.x, b = blockIdx.y;
    int t = threadIdx.x;                 // t covers d = 4t..4t+3
    int s = g_start[g], e_end = g_start[g + 1];

    float4 den = make_float4(0.f, 0.f, 0.f, 0.f);
    float4 num = make_float4(0.f, 0.f, 0.f, 0.f);
    const float4* LV4 = (const float4*)g_LV;

    for (int j = s; j < e_end; j++) {
        int e = g_order[j];
        size_t row = (size_t)b * E_ + e;
        float4 L = LV4[row * 256 + t];
        float4 V = LV4[row * 256 + 128 + t];
        float e0 = __expf(L.x), e1 = __expf(L.y), e2 = __expf(L.z), e3 = __expf(L.w);
        den.x += e0; den.y += e1; den.z += e2; den.w += e3;
        num.x += e0 * V.x; num.y += e1 * V.y; num.z += e2 * V.z; num.w += e3 * V.w;
    }
    float y0 = (den.x > 0.f) ? num.x / den.x : 0.f;
    float y1 = (den.y > 0.f) ? num.y / den.y : 0.f;
    float y2 = (den.z > 0.f) ? num.z / den.z : 0.f;
    float y3 = (den.w > 0.f) ? num.w / den.w : 0.f;

    __nv_bfloat16 h0 = __float2bfloat16(y0), h1 = __float2bfloat16(y1);
    __nv_bfloat16 h2 = __float2bfloat16(y2), h3 = __float2bfloat16(y3);
    __nv_bfloat16 l0 = __float2bfloat16(y0 - __bfloat162float(h0));
    __nv_bfloat16 l1 = __float2bfloat16(y1 - __bfloat162float(h1));
    __nv_bfloat16 l2 = __float2bfloat16(y2 - __bfloat162float(h2));
    __nv_bfloat16 l3 = __float2bfloat16(y3 - __bfloat162float(h3));

    size_t o2 = ((size_t)b * G_ + g) * 256 + (size_t)t * 2;   // bf16x2 index
    ((__nv_bfloat162*)g_yhi)[o2]     = __halves2bfloat162(h0, h1);
    ((__nv_bfloat162*)g_yhi)[o2 + 1] = __halves2bfloat162(h2, h3);
    ((__nv_bfloat162*)g_ylo)[o2]     = __halves2bfloat162(l0, l1);
    ((__nv_bfloat162*)g_ylo)[o2 + 1] = __halves2bfloat162(l2, l3);
}

// ---------------- gather out[b,e,:] = of[b, ix[e], :] -------------------------------------
__global__ void gather_k(const int* __restrict__ ix, float4* __restrict__ out) {
    size_t i = (size_t)blockIdx.x * blockDim.x + threadIdx.x;
    const size_t n4 = (size_t)B_ * E_ * (D_ / 4);
    if (i >= n4) return;
    int    d4 = (int)(i & 127);
    size_t be = i >> 7;
    int    e  = (int)(be & (E_ - 1));
    int    b  = (int)(be >> 15);
    const float4* of4 = (const float4*)g_of;
    out[i] = of4[((size_t)b * G_ + ix[e]) * 128 + d4];
}

// ---------------- launcher -----------------------------------------------------------------
extern "C" void kernel_launch(void* const* d_in, const int* in_sizes, int n_in,
                              void* d_out, int out_size) {
    const float* x  = (const float*)d_in[0];
    const int*   ix = (const int*)d_in[1];
    const float* Wf = (const float*)d_in[2];
    const float* bf = (const float*)d_in[3];
    const float* Wg = (const float*)d_in[4];
    const float* bg = (const float*)d_in[5];
    const float* Wh = (const float*)d_in[6];
    const float* bh = (const float*)d_in[7];
    float* out = (float*)d_out;

    float* pLV;  cudaGetSymbolAddress((void**)&pLV, g_LV);
    float* pOF;  cudaGetSymbolAddress((void**)&pOF, g_of);
    __nv_bfloat16 *xhi, *xlo, *wshi, *wslo, *whhi, *whlo, *yhi, *ylo;
    cudaGetSymbolAddress((void**)&xhi, g_xhi);
    cudaGetSymbolAddress((void**)&xlo, g_xlo);
    cudaGetSymbolAddress((void**)&wshi, g_wstkhi);
    cudaGetSymbolAddress((void**)&wslo, g_wstklo);
    cudaGetSymbolAddress((void**)&whhi, g_whhi);
    cudaGetSymbolAddress((void**)&whlo, g_whlo);
    cudaGetSymbolAddress((void**)&yhi, g_yhi);
    cudaGetSymbolAddress((void**)&ylo, g_ylo);
    float* pbstk; cudaGetSymbolAddress((void**)&pbstk, g_bstk);

    cudaFuncSetAttribute(gemm3, cudaFuncAttributeMaxDynamicSharedMemorySize, SMEM_GEMM);

    const int T = 256;

    // 0) conversions: x -> hi/lo; Wg/Wf stacked; Wh; bias stack
    {
        size_t n4 = (size_t)B_ * E_ * D_ / 4;
        cvt_hilo4<<<(unsigned)((n4 + T - 1) / T), T>>>(x, xhi, xlo, n4);
        size_t w4 = (size_t)D_ * D_ / 4;
        cvt_hilo4<<<(unsigned)((w4 + T - 1) / T), T>>>(Wg, wshi, wslo, w4);
        cvt_hilo4<<<(unsigned)((w4 + T - 1) / T), T>>>(Wf, wshi + 512 * 512, wslo + 512 * 512, w4);
        cvt_hilo4<<<(unsigned)((w4 + T - 1) / T), T>>>(Wh, whhi, whlo, w4);
        stack_bias<<<2, 256>>>(bg, bf);
    }

    // 1) CSR build from ix
    zero_cnt<<<G_ / T, T>>>();
    hist_k<<<E_ / T, T>>>(ix);
    scan_k<<<1, 1024>>>();
    scatter_k<<<E_ / T, T>>>(ix);

    // 2) projections (stacked): LV = X @ [Wg;Wf]^T + [bg;bf]
    {
        dim3 grid(4, (B_ * E_) / 128);
        gemm3<<<grid, 512, SMEM_GEMM>>>(xhi, xlo, wshi, wslo, pbstk, pLV, 1024);
    }

    // 3) per-group softmax-weighted reduce -> y (hi/lo bf16, fused)
    {
        dim3 grid(G_, B_);
        segreduce_k<<<grid, 128>>>();
    }

    // 4) of = y @ Wh^T + bh
    {
        dim3 grid(2, (B_ * G_) / 128);
        gemm3<<<grid, 512, SMEM_GEMM>>>(yhi, ylo, whhi, whlo, bh, pOF, 512);
    }

    // 5) gather to edges
    {
        size_t n4 = (size_t)B_ * E_ * (D_ / 4);
        gather_k<<<(unsigned)((n4 + T - 1) / T), T>>>(ix, (float4*)out);
    }
}

// round 5
// speedup vs baseline: 3.4206x; 1.2614x over previous
#include <cuda_runtime.h>
#include <cuda_fp16.h>
#include <cstdint>
#include <math.h>

#define B_ 2
#define E_ 32768
#define D_ 512
#define G_ 2048

// ---------------- scratch ------------------------------------------------------------
__device__ float  g_LV[(size_t)B_ * E_ * 1024];     // [m, 0:512]=logits, [m,512:1024]=vals
__device__ __half g_xhi[(size_t)B_ * E_ * D_];
__device__ __half g_xlo[(size_t)B_ * E_ * D_];
__device__ __half g_wstk[1024 * 512];               // [Wg; Wf] fp16
__device__ float  g_bstk[1024];
__device__ __half g_wh[D_ * D_];
__device__ __half g_yhi[(size_t)B_ * G_ * D_], g_ylo[(size_t)B_ * G_ * D_];
__device__ float  g_of[(size_t)B_ * G_ * D_];
__device__ int    g_cnt[G_], g_start[G_ + 1], g_cursor[G_], g_order[E_];

// ---------------- PTX helpers ---------------------------------------------------------
__device__ __forceinline__ uint32_t smem_u32(const void* p) {
    uint32_t a;
    asm("{ .reg .u64 t; cvta.to.shared.u64 t, %1; cvt.u32.u64 %0, t; }" : "=r"(a) : "l"(p));
    return a;
}
__device__ __forceinline__ void cp16(uint32_t s, const void* g) {
    asm volatile("cp.async.cg.shared.global [%0], [%1], 16;" :: "r"(s), "l"(g));
}
#define CP_COMMIT() asm volatile("cp.async.commit_group;" ::: "memory")
#define CP_WAIT(n)  asm volatile("cp.async.wait_group %0;" :: "n"(n) : "memory")

__device__ __forceinline__ void ldsm4(uint32_t* r, uint32_t addr) {
    asm volatile("ldmatrix.sync.aligned.m8n8.x4.shared.b16 {%0,%1,%2,%3}, [%4];"
                 : "=r"(r[0]), "=r"(r[1]), "=r"(r[2]), "=r"(r[3]) : "r"(addr));
}
__device__ __forceinline__ void mma_f16(float* c, const uint32_t* a, const uint32_t* b) {
    asm volatile(
        "mma.sync.aligned.m16n8k16.row.col.f32.f16.f16.f32 "
        "{%0,%1,%2,%3}, {%4,%5,%6,%7}, {%8,%9}, {%0,%1,%2,%3};"
        : "+f"(c[0]), "+f"(c[1]), "+f"(c[2]), "+f"(c[3])
        : "r"(a[0]), "r"(a[1]), "r"(a[2]), "r"(a[3]), "r"(b[0]), "r"(b[1]));
}

// ---------------- conversions -----------------------------------------------------------
// x -> fp16 hi/lo split (float4 vectorized)
__global__ void cvt_hilo4(const float* __restrict__ s, __half* __restrict__ hi,
                          __half* __restrict__ lo, size_t n4) {
    size_t i = (size_t)blockIdx.x * blockDim.x + threadIdx.x;
    if (i >= n4) return;
    float4 f = ((const float4*)s)[i];
    __half h0 = __float2half(f.x), h1 = __float2half(f.y);
    __half h2 = __float2half(f.z), h3 = __float2half(f.w);
    __half l0 = __float2half(f.x - __half2float(h0));
    __half l1 = __float2half(f.y - __half2float(h1));
    __half l2 = __float2half(f.z - __half2float(h2));
    __half l3 = __float2half(f.w - __half2float(h3));
    ((__half2*)hi)[2 * i]     = __halves2half2(h0, h1);
    ((__half2*)hi)[2 * i + 1] = __halves2half2(h2, h3);
    ((__half2*)lo)[2 * i]     = __halves2half2(l0, l1);
    ((__half2*)lo)[2 * i + 1] = __halves2half2(l2, l3);
}

// weights -> single fp16
__global__ void cvt_f16(const float* __restrict__ s, __half* __restrict__ d, size_t n4) {
    size_t i = (size_t)blockIdx.x * blockDim.x + threadIdx.x;
    if (i >= n4) return;
    float4 f = ((const float4*)s)[i];
    ((__half2*)d)[2 * i]     = __halves2half2(__float2half(f.x), __float2half(f.y));
    ((__half2*)d)[2 * i + 1] = __halves2half2(__float2half(f.z), __float2half(f.w));
}

__global__ void stack_bias(const float* __restrict__ bg, const float* __restrict__ bf) {
    int t = threadIdx.x + blockIdx.x * blockDim.x;
    if (t < 512) { g_bstk[t] = bg[t]; g_bstk[512 + t] = bf[t]; }
}

// ---------------- CSR build -------------------------------------------------------------
__global__ void zero_cnt() {
    int t = threadIdx.x + blockIdx.x * blockDim.x;
    if (t < G_) g_cnt[t] = 0;
}
__global__ void hist_k(const int* __restrict__ ix) {
    int e = threadIdx.x + blockIdx.x * blockDim.x;
    if (e < E_) atomicAdd(&g_cnt[ix[e]], 1);
}
__global__ void scan_k() {   // 1 block, 1024 threads, 2 elems each
    __shared__ int ps[1024];
    int t = threadIdx.x;
    int c0 = g_cnt[2 * t], c1 = g_cnt[2 * t + 1];
    ps[t] = c0 + c1;
    __syncthreads();
#pragma unroll
    for (int off = 1; off < 1024; off <<= 1) {
        int v = (t >= off) ? ps[t - off] : 0;
        __syncthreads();
        ps[t] += v;
        __syncthreads();
    }
    int excl = (t > 0) ? ps[t - 1] : 0;
    g_start[2 * t] = excl;          g_cursor[2 * t] = excl;
    g_start[2 * t + 1] = excl + c0; g_cursor[2 * t + 1] = excl + c0;
    if (t == 1023) g_start[2048] = ps[1023];
}
__global__ void scatter_k(const int* __restrict__ ix) {
    int e = threadIdx.x + blockIdx.x * blockDim.x;
    if (e >= E_) return;
    int idx = atomicAdd(&g_cursor[ix[e]], 1);
    g_order[idx] = e;
}

// ---------------- fp16x2 GEMM on mma.sync, 4-stage pipeline ------------------------------
// C[m][n] = sum_k A[m][k]*W[n][k] + bias[n]; A = Ah+Al (fp16 split), W = fp16.
// K=512, CTA tile 128x256, BK=32, 512 threads (4x4 warps, warp tile 32x64).
#define PITCH 80
#define ABUF  10240            // 128 rows * 80
#define BBUF  20480            // 256 rows * 80
#define BUFSZ 40960            // Ah + Al + B per stage
#define NSTAGE 4
#define SMEM_GEMM (NSTAGE * BUFSZ)  // 163840

__global__ __launch_bounds__(512, 1)
void gemm2t(const __half* __restrict__ Ahi, const __half* __restrict__ Alo,
            const __half* __restrict__ Bw,
            const float* __restrict__ bias, float* __restrict__ C, int ldc) {
    extern __shared__ char smem[];
    const uint32_t sb = smem_u32(smem);
    const int tid = threadIdx.x, lane = tid & 31, wid = tid >> 5;
    const int wm = wid >> 2, wn = wid & 3;
    const int m0 = blockIdx.y * 128, n0 = blockIdx.x * 256;

    float acc[2][8][4];
#pragma unroll
    for (int mt = 0; mt < 2; mt++)
#pragma unroll
        for (int nt = 0; nt < 8; nt++)
#pragma unroll
            for (int q = 0; q < 4; q++) acc[mt][nt][q] = 0.0f;

    // 2048 16B chunks per stage, 4 per thread
    auto load_buf = [&](int kc, int buf) {
        const int k0 = kc * 32;
        const uint32_t bb = sb + buf * BUFSZ;
#pragma unroll
        for (int t = 0; t < 4; t++) {
            int q = tid + t * 512;
            const __half* src;
            uint32_t base;
            int qq;
            if (q < 512)       { src = Ahi; base = 0;        qq = q; }
            else if (q < 1024) { src = Alo; base = ABUF;     qq = q - 512; }
            else               { src = Bw;  base = 2 * ABUF; qq = q - 1024; }
            int row = qq >> 2, c = qq & 3;
            int grow = (q < 1024) ? (m0 + row) : (n0 + row);
            cp16(bb + base + (uint32_t)(row * PITCH + c * 16),
                 src + (size_t)grow * 512 + k0 + c * 8);
        }
    };

    load_buf(0, 0); CP_COMMIT();
    load_buf(1, 1); CP_COMMIT();
    load_buf(2, 2); CP_COMMIT();

    const uint32_t a_lane = (uint32_t)((wm * 32 + (lane & 15)) * PITCH + (lane >> 4) * 16);
    const uint32_t b_lane = (uint32_t)((wn * 64 + ((lane >> 4) & 1) * 8 + (lane & 7)) * PITCH +
                                       ((lane >> 3) & 1) * 16);

    for (int kc = 0; kc < 16; kc++) {
        CP_WAIT(2);
        __syncthreads();
        if (kc + 3 < 16) load_buf(kc + 3, (kc + 3) & (NSTAGE - 1));
        CP_COMMIT();

        const uint32_t bb = sb + (kc & (NSTAGE - 1)) * BUFSZ;
#pragma unroll
        for (int ks = 0; ks < 2; ks++) {
            uint32_t ah[2][4], al[2][4];
            uint32_t aoff = a_lane + (uint32_t)(ks * 32);
            ldsm4(ah[0], bb + aoff);
            ldsm4(ah[1], bb + aoff + 16 * PITCH);
            ldsm4(al[0], bb + ABUF + aoff);
            ldsm4(al[1], bb + ABUF + aoff + 16 * PITCH);
#pragma unroll
            for (int np = 0; np < 4; np++) {
                uint32_t boff = b_lane + (uint32_t)(np * 16 * PITCH + ks * 32);
                uint32_t b4[4];
                ldsm4(b4, bb + 2 * ABUF + boff);
#pragma unroll
                for (int mt = 0; mt < 2; mt++) {
                    mma_f16(acc[mt][2 * np],     ah[mt], b4);
                    mma_f16(acc[mt][2 * np + 1], ah[mt], b4 + 2);
                    mma_f16(acc[mt][2 * np],     al[mt], b4);
                    mma_f16(acc[mt][2 * np + 1], al[mt], b4 + 2);
                }
            }
        }
    }

    // epilogue: bias + direct stores
#pragma unroll
    for (int mt = 0; mt < 2; mt++) {
        int r0 = m0 + wm * 32 + mt * 16 + (lane >> 2);
#pragma unroll
        for (int nt = 0; nt < 8; nt++) {
            int col = n0 + wn * 64 + nt * 8 + (lane & 3) * 2;
            float b0 = bias[col], b1 = bias[col + 1];
            float2 v0 = make_float2(acc[mt][nt][0] + b0, acc[mt][nt][1] + b1);
            float2 v1 = make_float2(acc[mt][nt][2] + b0, acc[mt][nt][3] + b1);
            *(float2*)&C[(size_t)r0 * ldc + col]       = v0;
            *(float2*)&C[(size_t)(r0 + 8) * ldc + col] = v1;
        }
    }
}

// ---------------- per-group softmax-weighted reduction -----------------------------------
// One block per (g,b); fused exp / weighted-sum / normalize; emits y as fp16 hi/lo.
__global__ __launch_bounds__(128)
void segreduce_k() {
    int g = blockIdx.x, b = blockIdx.y;
    int t = threadIdx.x;                 // t covers d = 4t..4t+3
    int s = g_start[g], e_end = g_start[g + 1];

    float4 den = make_float4(0.f, 0.f, 0.f, 0.f);
    float4 num = make_float4(0.f, 0.f, 0.f, 0.f);
    const float4* LV4 = (const float4*)g_LV;

    for (int j = s; j < e_end; j++) {
        int e = g_order[j];
        size_t row = (size_t)b * E_ + e;
        float4 L = LV4[row * 256 + t];
        float4 V = LV4[row * 256 + 128 + t];
        float e0 = __expf(L.x), e1 = __expf(L.y), e2 = __expf(L.z), e3 = __expf(L.w);
        den.x += e0; den.y += e1; den.z += e2; den.w += e3;
        num.x += e0 * V.x; num.y += e1 * V.y; num.z += e2 * V.z; num.w += e3 * V.w;
    }
    float y0 = (den.x > 0.f) ? num.x / den.x : 0.f;
    float y1 = (den.y > 0.f) ? num.y / den.y : 0.f;
    float y2 = (den.z > 0.f) ? num.z / den.z : 0.f;
    float y3 = (den.w > 0.f) ? num.w / den.w : 0.f;

    __half h0 = __float2half(y0), h1 = __float2half(y1);
    __half h2 = __float2half(y2), h3 = __float2half(y3);
    __half l0 = __float2half(y0 - __half2float(h0));
    __half l1 = __float2half(y1 - __half2float(h1));
    __half l2 = __float2half(y2 - __half2float(h2));
    __half l3 = __float2half(y3 - __half2float(h3));

    size_t o2 = ((size_t)b * G_ + g) * 256 + (size_t)t * 2;   // half2 index
    ((__half2*)g_yhi)[o2]     = __halves2half2(h0, h1);
    ((__half2*)g_yhi)[o2 + 1] = __halves2half2(h2, h3);
    ((__half2*)g_ylo)[o2]     = __halves2half2(l0, l1);
    ((__half2*)g_ylo)[o2 + 1] = __halves2half2(l2, l3);
}

// ---------------- gather out[b,e,:] = of[b, ix[e], :] -------------------------------------
__global__ void gather_k(const int* __restrict__ ix, float4* __restrict__ out) {
    size_t i = (size_t)blockIdx.x * blockDim.x + threadIdx.x;
    const size_t n4 = (size_t)B_ * E_ * (D_ / 4);
    if (i >= n4) return;
    int    d4 = (int)(i & 127);
    size_t be = i >> 7;
    int    e  = (int)(be & (E_ - 1));
    int    b  = (int)(be >> 15);
    const float4* of4 = (const float4*)g_of;
    out[i] = of4[((size_t)b * G_ + ix[e]) * 128 + d4];
}

// ---------------- launcher -----------------------------------------------------------------
extern "C" void kernel_launch(void* const* d_in, const int* in_sizes, int n_in,
                              void* d_out, int out_size) {
    const float* x  = (const float*)d_in[0];
    const int*   ix = (const int*)d_in[1];
    const float* Wf = (const float*)d_in[2];
    const float* bf = (const float*)d_in[3];
    const float* Wg = (const float*)d_in[4];
    const float* bg = (const float*)d_in[5];
    const float* Wh = (const float*)d_in[6];
    const float* bh = (const float*)d_in[7];
    float* out = (float*)d_out;

    float* pLV;  cudaGetSymbolAddress((void**)&pLV, g_LV);
    float* pOF;  cudaGetSymbolAddress((void**)&pOF, g_of);
    __half *xhi, *xlo, *wstk, *wh, *yhi, *ylo;
    cudaGetSymbolAddress((void**)&xhi, g_xhi);
    cudaGetSymbolAddress((void**)&xlo, g_xlo);
    cudaGetSymbolAddress((void**)&wstk, g_wstk);
    cudaGetSymbolAddress((void**)&wh, g_wh);
    cudaGetSymbolAddress((void**)&yhi, g_yhi);
    cudaGetSymbolAddress((void**)&ylo, g_ylo);
    float* pbstk; cudaGetSymbolAddress((void**)&pbstk, g_bstk);

    cudaFuncSetAttribute(gemm2t, cudaFuncAttributeMaxDynamicSharedMemorySize, SMEM_GEMM);

    const int T = 256;

    // 0) conversions: x -> fp16 hi/lo; weights -> fp16; bias stack
    {
        size_t n4 = (size_t)B_ * E_ * D_ / 4;
        cvt_hilo4<<<(unsigned)((n4 + T - 1) / T), T>>>(x, xhi, xlo, n4);
        size_t w4 = (size_t)D_ * D_ / 4;
        cvt_f16<<<(unsigned)((w4 + T - 1) / T), T>>>(Wg, wstk, w4);
        cvt_f16<<<(unsigned)((w4 + T - 1) / T), T>>>(Wf, wstk + 512 * 512, w4);
        cvt_f16<<<(unsigned)((w4 + T - 1) / T), T>>>(Wh, wh, w4);
        stack_bias<<<2, 256>>>(bg, bf);
    }

    // 1) CSR build from ix
    zero_cnt<<<G_ / T, T>>>();
    hist_k<<<E_ / T, T>>>(ix);
    scan_k<<<1, 1024>>>();
    scatter_k<<<E_ / T, T>>>(ix);

    // 2) projections (stacked): LV = X @ [Wg;Wf]^T + [bg;bf]
    {
        dim3 grid(4, (B_ * E_) / 128);
        gemm2t<<<grid, 512, SMEM_GEMM>>>(xhi, xlo, wstk, pbstk, pLV, 1024);
    }

    // 3) per-group softmax-weighted reduce -> y (fp16 hi/lo, fused normalize)
    {
        dim3 grid(G_, B_);
        segreduce_k<<<grid, 128>>>();
    }

    // 4) of = y @ Wh^T + bh
    {
        dim3 grid(2, (B_ * G_) / 128);
        gemm2t<<<grid, 512, SMEM_GEMM>>>(yhi, ylo, wh, bh, pOF, 512);
    }

    // 5) gather to edges
    {
        size_t n4 = (size_t)B_ * E_ * (D_ / 4);
        gather_k<<<(unsigned)((n4 + T - 1) / T), T>>>(ix, (float4*)out);
    }
}